// round 15
// baseline (speedup 1.0000x reference)
#include <cuda_runtime.h>
#include <cuda_fp16.h>
#include <cstdint>

// out[m, e*32+k] = sum_n A[m,n] * W[e,n,k]
// => C[8192,2048] = A[8192,1024] x B[1024,2048], B[n, e*32+k] = W[e,n,k]
// R15: prep convert at MLP8 (32 elems/thread); epilogue streaming stores;
// branchless nxt-fragment preload. GEMM core unchanged from R14
// (fp16 m16n8k16, 128x128, 3 stages, 2 CTAs/SM, buried-sync pipeline).

#define M_DIM 8192
#define KR    1024
#define NOUT  2048
#define E_DIM 64

#define BM 128
#define BN 128
#define BK 64                            // fp16 elems per k-tile = 128B row
#define STAGES 3
#define KTILES (KR / BK)                 // 16

#define A_STAGE (BM * BK * 2)            // 16 KB
#define B_STAGE (BN * BK * 2)            // 16 KB
#define STAGE_BYTES (A_STAGE + B_STAGE)  // 32 KB
#define SMEM_TOTAL (STAGES * STAGE_BYTES)// 96 KB -> 2 CTAs/SM

#define CONV_BLOCKS (M_DIM * KR / (256 * 32))   // 1024
#define TRANS_BLOCKS ((KR / 32) * E_DIM)        // 2048

__device__ __half g_Ah[(size_t)M_DIM * KR];   // 16 MB: A in fp16
__device__ __half g_Bh[(size_t)NOUT * KR];    // 4 MB: W transposed fp16, [col][n]

// ---------------- helpers ----------------
__device__ __forceinline__ uint32_t smem_u32(const void* p) {
    uint32_t a;
    asm("{ .reg .u64 t; cvta.to.shared.u64 t, %1; cvt.u32.u64 %0, t; }" : "=r"(a) : "l"(p));
    return a;
}
__device__ __forceinline__ void cp16(uint32_t dst, const void* src) {
    asm volatile("cp.async.cg.shared.global [%0], [%1], 16;" :: "r"(dst), "l"(src) : "memory");
}
#define CP_COMMIT() asm volatile("cp.async.commit_group;" ::: "memory")
#define CP_WAIT1()  asm volatile("cp.async.wait_group 1;" ::: "memory")

__device__ __forceinline__ void ldsm4(uint32_t* r, uint32_t addr) {
    asm volatile("ldmatrix.sync.aligned.m8n8.x4.shared.b16 {%0,%1,%2,%3}, [%4];"
                 : "=r"(r[0]), "=r"(r[1]), "=r"(r[2]), "=r"(r[3]) : "r"(addr));
}
__device__ __forceinline__ void mma16(float* c, const uint32_t* a, uint32_t b0, uint32_t b1) {
    asm volatile("mma.sync.aligned.m16n8k16.row.col.f32.f16.f16.f32 "
                 "{%0,%1,%2,%3}, {%4,%5,%6,%7}, {%8,%9}, {%0,%1,%2,%3};"
                 : "+f"(c[0]), "+f"(c[1]), "+f"(c[2]), "+f"(c[3])
                 : "r"(a[0]), "r"(a[1]), "r"(a[2]), "r"(a[3]), "r"(b0), "r"(b1));
}
__device__ __forceinline__ void st_cs_f2(float* p, float x, float y) {
    asm volatile("st.global.cs.v2.f32 [%0], {%1, %2};" :: "l"(p), "f"(x), "f"(y) : "memory");
}
// swizzled byte offset for K-major tile, 128B rows: row r, 16B chunk c
__device__ __forceinline__ uint32_t swoff(int r, int c) {
    return (uint32_t)(r * 128 + ((c ^ (r & 7)) << 4));
}

// ---------------- fused prep kernel ----------------
// blocks [0, CONV_BLOCKS): convert A fp32->fp16, 32 elems/thread, MLP 8
// blocks [CONV_BLOCKS, +TRANS_BLOCKS): transpose+convert W
__global__ void prep_fused(const float* __restrict__ A, const float* __restrict__ W) {
    __shared__ float t[32][33];
    const int tid = threadIdx.x;

    if (blockIdx.x < CONV_BLOCKS) {
        const size_t i = ((size_t)blockIdx.x * 256 + tid) * 32;
        float4 v[8];
        #pragma unroll
        for (int j = 0; j < 8; j++) v[j] = *(const float4*)(A + i + j * 4);
        __half2 h[16];
        #pragma unroll
        for (int j = 0; j < 8; j++) {
            h[j * 2 + 0] = __floats2half2_rn(v[j].x, v[j].y);
            h[j * 2 + 1] = __floats2half2_rn(v[j].z, v[j].w);
        }
        #pragma unroll
        for (int j = 0; j < 4; j++)
            *(uint4*)(g_Ah + i + j * 8) = *(uint4*)(h + j * 4);
    } else {
        const int q = blockIdx.x - CONV_BLOCKS;
        const int e = q >> 5;                 // expert
        const int n0 = (q & 31) * 32;         // n-tile
        {
            const int i = tid >> 3, k4 = (tid & 7) * 4;
            float4 v = *(const float4*)(W + ((size_t)e * KR + n0 + i) * 32 + k4);
            t[i][k4 + 0] = v.x; t[i][k4 + 1] = v.y;
            t[i][k4 + 2] = v.z; t[i][k4 + 3] = v.w;
        }
        __syncthreads();
        {
            const int k = tid >> 3, j4 = (tid & 7) * 4;
            __half2 h0 = __floats2half2_rn(t[j4 + 0][k], t[j4 + 1][k]);
            __half2 h1 = __floats2half2_rn(t[j4 + 2][k], t[j4 + 3][k]);
            __half* dst = g_Bh + ((size_t)(e * 32 + k)) * KR + n0 + j4;
            *(__half2*)(dst + 0) = h0;
            *(__half2*)(dst + 2) = h1;
        }
    }
}

// ---------------- main GEMM ----------------
__global__ __launch_bounds__(128, 2)
void gemm_fp16_mma(float* __restrict__ out) {
    extern __shared__ char smem[];
    const uint32_t sb = smem_u32(smem);
    const int tid  = threadIdx.x;
    const int lane = tid & 31;
    const int wid  = tid >> 5;
    const int warp_m = wid & 1;     // 2 warps over M  -> 64 rows each
    const int warp_n = wid >> 1;    // 2 warps over N  -> 64 cols each
    const int rowBase = blockIdx.y * BM;
    const int colBase = blockIdx.x * BN;

    // ---- loop-invariant cp.async addressing ----
    const int ldr = tid >> 3;                 // 0..15
    const int ldc = tid & 7;                  // 16B chunk (8 fp16)
    const __half* aSrc = g_Ah + ((size_t)rowBase + ldr) * KR + ldc * 8;
    const __half* bSrc = g_Bh + ((size_t)colBase + ldr) * KR + ldc * 8;
    const uint32_t aDst0 = sb + swoff(ldr, ldc);            // +2048*i for row+16i
    const uint32_t bDst0 = sb + A_STAGE + swoff(ldr, ldc);

    // ---- loop-invariant ldsm addressing (fp16 m16n8k16 canonical) ----
    const int lrow  = lane & 15;              // row within 16-row frag
    const int lxor  = lane & 7;               // swizzle xor
    const int lhalf = lane >> 4;              // chunk +0 / +1
    const uint32_t aBase = sb + (uint32_t)((warp_m * 64 + lrow) * 128);
    const uint32_t bBase = sb + A_STAGE + (uint32_t)((warp_n * 64 + lrow) * 128);
    uint32_t coff[4];
    #pragma unroll
    for (int ks = 0; ks < 4; ks++)
        coff[ks] = (uint32_t)(((ks * 2 + lhalf) ^ lxor) << 4);

    float acc[4][8][4];
    #pragma unroll
    for (int mi = 0; mi < 4; mi++)
        #pragma unroll
        for (int ni = 0; ni < 8; ni++)
            #pragma unroll
            for (int q = 0; q < 4; q++) acc[mi][ni][q] = 0.0f;

    // ---- fragment buffers (parity double-buffered, static indices) ----
    uint32_t a0[4][4], a1[4][4], b0[4][4], b1[4][4];

#define LDFRAG0(soff, ks) do { \
    _Pragma("unroll") for (int mi = 0; mi < 4; mi++) \
        ldsm4(a0[mi], aBase + (soff) + mi * 2048u + coff[ks]); \
    _Pragma("unroll") for (int nb = 0; nb < 4; nb++) \
        ldsm4(b0[nb], bBase + (soff) + nb * 2048u + coff[ks]); \
} while (0)
#define LDFRAG1(soff, ks) do { \
    _Pragma("unroll") for (int mi = 0; mi < 4; mi++) \
        ldsm4(a1[mi], aBase + (soff) + mi * 2048u + coff[ks]); \
    _Pragma("unroll") for (int nb = 0; nb < 4; nb++) \
        ldsm4(b1[nb], bBase + (soff) + nb * 2048u + coff[ks]); \
} while (0)
#define MMA_BURST(ab, bb) do { \
    _Pragma("unroll") for (int mi = 0; mi < 4; mi++) \
        _Pragma("unroll") for (int nb = 0; nb < 4; nb++) { \
            mma16(acc[mi][nb * 2 + 0], ab[mi], bb[nb][0], bb[nb][2]); \
            mma16(acc[mi][nb * 2 + 1], ab[mi], bb[nb][1], bb[nb][3]); \
        } \
} while (0)

    // ---- producer: issue one stage's cp.asyncs ----
#define ISSUE_STAGE(soff, aP, bP) do { \
    _Pragma("unroll") for (int i = 0; i < 8; i++) \
        cp16(aDst0 + (soff) + i * 2048u, (aP) + (size_t)i * 16 * KR); \
    _Pragma("unroll") for (int i = 0; i < 8; i++) \
        cp16(bDst0 + (soff) + i * 2048u, (bP) + (size_t)i * 16 * KR); \
} while (0)

    // ---- prologue: stages 0,1 in flight; wait s0; preload ks0 frags ----
    ISSUE_STAGE(0, aSrc, bSrc); CP_COMMIT();
    ISSUE_STAGE(STAGE_BYTES, aSrc + BK, bSrc + BK); CP_COMMIT();
    CP_WAIT1();
    __syncthreads();
    LDFRAG0(0, 0);

    uint32_t cons_off = 0;
    uint32_t prod_off = 2 * STAGE_BYTES;
    const __half* aP = aSrc + 2 * BK;
    const __half* bP = bSrc + 2 * BK;

    for (int kt = 0; kt < KTILES; kt++) {
        const uint32_t cur = cons_off;
        const uint32_t nxt = (cur + STAGE_BYTES == STAGES * STAGE_BYTES) ? 0u : cur + STAGE_BYTES;

        // top: issue stage kt+2 NOW (slot holds kt-1, fully read before last sync).
        // Unconditional commit keeps group numbering uniform for CP_WAIT1.
        if (kt + 2 < KTILES) {
            ISSUE_STAGE(prod_off, aP, bP);
            aP += BK; bP += BK;
        }
        CP_COMMIT();

        // ks0: frags in buf0; preload ks1 -> buf1
        LDFRAG1(cur, 1);
        MMA_BURST(a0, b0);
        // ks1: preload ks2 -> buf0
        LDFRAG0(cur, 2);
        MMA_BURST(a1, b1);
        // ks2: drain group kt+1 (leave kt+2 flying), preload ks3 -> buf1
        CP_WAIT1();
        LDFRAG1(cur, 3);
        MMA_BURST(a0, b0);
        // barrier: (a) all warps see stage kt+1, (b) safe to overwrite stage kt-1
        __syncthreads();
        // ks3: preload next kt's ks0 -> buf0 (branchless: last-iter read is
        // stale-but-unused data from a resident stage); mma burst
        LDFRAG0(nxt, 0);
        MMA_BURST(a1, b1);

        cons_off = nxt;
        prod_off = (prod_off + STAGE_BYTES == STAGES * STAGE_BYTES) ? 0u : prod_off + STAGE_BYTES;
    }

    // ---- epilogue: streaming stores (out is never re-read) ----
    const int g = lane >> 2, t = lane & 3;
    #pragma unroll
    for (int mi = 0; mi < 4; mi++) {
        const int r0 = rowBase + warp_m * 64 + mi * 16 + g;
        #pragma unroll
        for (int ni = 0; ni < 8; ni++) {
            const int col = colBase + warp_n * 64 + ni * 8 + t * 2;
            st_cs_f2(out + (size_t)r0 * NOUT + col, acc[mi][ni][0], acc[mi][ni][1]);
            st_cs_f2(out + (size_t)(r0 + 8) * NOUT + col, acc[mi][ni][2], acc[mi][ni][3]);
        }
    }
}

extern "C" void kernel_launch(void* const* d_in, const int* in_sizes, int n_in,
                              void* d_out, int out_size)
{
    const float* A = (const float*)d_in[0];
    const float* W = (const float*)d_in[1];
    float* out = (float*)d_out;

    cudaFuncSetAttribute(gemm_fp16_mma, cudaFuncAttributeMaxDynamicSharedMemorySize, SMEM_TOTAL);

    prep_fused<<<CONV_BLOCKS + TRANS_BLOCKS, 256>>>(A, W);
    gemm_fp16_mma<<<dim3(NOUT / BN, M_DIM / BM), 128, SMEM_TOTAL>>>(out);
}

// round 16
// speedup vs baseline: 1.0491x; 1.0491x over previous
#include <cuda_runtime.h>
#include <cuda_fp16.h>
#include <cstdint>

// out[m, e*32+k] = sum_n A[m,n] * W[e,n,k]
// => C[8192,2048] = A[8192,1024] x B[1024,2048], B[n, e*32+k] = W[e,n,k]
// R16: R15 GEMM (fp16 m16n8k16, 128x128, 3 stages, 2 CTAs/SM, st.cs epilogue,
// branchless preload) + R14 prep (MLP4 convert, 2048+2048 balanced fused grid).

#define M_DIM 8192
#define KR    1024
#define NOUT  2048
#define E_DIM 64

#define BM 128
#define BN 128
#define BK 64                            // fp16 elems per k-tile = 128B row
#define STAGES 3
#define KTILES (KR / BK)                 // 16

#define A_STAGE (BM * BK * 2)            // 16 KB
#define B_STAGE (BN * BK * 2)            // 16 KB
#define STAGE_BYTES (A_STAGE + B_STAGE)  // 32 KB
#define SMEM_TOTAL (STAGES * STAGE_BYTES)// 96 KB -> 2 CTAs/SM

#define CONV_BLOCKS (M_DIM * KR / (256 * 16))   // 2048
#define TRANS_BLOCKS ((KR / 32) * E_DIM)        // 2048

__device__ __half g_Ah[(size_t)M_DIM * KR];   // 16 MB: A in fp16
__device__ __half g_Bh[(size_t)NOUT * KR];    // 4 MB: W transposed fp16, [col][n]

// ---------------- helpers ----------------
__device__ __forceinline__ uint32_t smem_u32(const void* p) {
    uint32_t a;
    asm("{ .reg .u64 t; cvta.to.shared.u64 t, %1; cvt.u32.u64 %0, t; }" : "=r"(a) : "l"(p));
    return a;
}
__device__ __forceinline__ void cp16(uint32_t dst, const void* src) {
    asm volatile("cp.async.cg.shared.global [%0], [%1], 16;" :: "r"(dst), "l"(src) : "memory");
}
#define CP_COMMIT() asm volatile("cp.async.commit_group;" ::: "memory")
#define CP_WAIT1()  asm volatile("cp.async.wait_group 1;" ::: "memory")

__device__ __forceinline__ void ldsm4(uint32_t* r, uint32_t addr) {
    asm volatile("ldmatrix.sync.aligned.m8n8.x4.shared.b16 {%0,%1,%2,%3}, [%4];"
                 : "=r"(r[0]), "=r"(r[1]), "=r"(r[2]), "=r"(r[3]) : "r"(addr));
}
__device__ __forceinline__ void mma16(float* c, const uint32_t* a, uint32_t b0, uint32_t b1) {
    asm volatile("mma.sync.aligned.m16n8k16.row.col.f32.f16.f16.f32 "
                 "{%0,%1,%2,%3}, {%4,%5,%6,%7}, {%8,%9}, {%0,%1,%2,%3};"
                 : "+f"(c[0]), "+f"(c[1]), "+f"(c[2]), "+f"(c[3])
                 : "r"(a[0]), "r"(a[1]), "r"(a[2]), "r"(a[3]), "r"(b0), "r"(b1));
}
__device__ __forceinline__ void st_cs_f2(float* p, float x, float y) {
    asm volatile("st.global.cs.v2.f32 [%0], {%1, %2};" :: "l"(p), "f"(x), "f"(y) : "memory");
}
// swizzled byte offset for K-major tile, 128B rows: row r, 16B chunk c
__device__ __forceinline__ uint32_t swoff(int r, int c) {
    return (uint32_t)(r * 128 + ((c ^ (r & 7)) << 4));
}

// ---------------- fused prep kernel ----------------
// blocks [0, CONV_BLOCKS): convert A fp32->fp16, 16 elems/thread, MLP 4
// blocks [CONV_BLOCKS, +TRANS_BLOCKS): transpose+convert W
__global__ void prep_fused(const float* __restrict__ A, const float* __restrict__ W) {
    __shared__ float t[32][33];
    const int tid = threadIdx.x;

    if (blockIdx.x < CONV_BLOCKS) {
        const size_t i = ((size_t)blockIdx.x * 256 + tid) * 16;
        float4 v0 = *(const float4*)(A + i);
        float4 v1 = *(const float4*)(A + i + 4);
        float4 v2 = *(const float4*)(A + i + 8);
        float4 v3 = *(const float4*)(A + i + 12);
        __half2 h[8];
        h[0] = __floats2half2_rn(v0.x, v0.y);
        h[1] = __floats2half2_rn(v0.z, v0.w);
        h[2] = __floats2half2_rn(v1.x, v1.y);
        h[3] = __floats2half2_rn(v1.z, v1.w);
        h[4] = __floats2half2_rn(v2.x, v2.y);
        h[5] = __floats2half2_rn(v2.z, v2.w);
        h[6] = __floats2half2_rn(v3.x, v3.y);
        h[7] = __floats2half2_rn(v3.z, v3.w);
        *(uint4*)(g_Ah + i)     = *(uint4*)(h + 0);
        *(uint4*)(g_Ah + i + 8) = *(uint4*)(h + 4);
    } else {
        const int q = blockIdx.x - CONV_BLOCKS;
        const int e = q >> 5;                 // expert
        const int n0 = (q & 31) * 32;         // n-tile
        {
            const int i = tid >> 3, k4 = (tid & 7) * 4;
            float4 v = *(const float4*)(W + ((size_t)e * KR + n0 + i) * 32 + k4);
            t[i][k4 + 0] = v.x; t[i][k4 + 1] = v.y;
            t[i][k4 + 2] = v.z; t[i][k4 + 3] = v.w;
        }
        __syncthreads();
        {
            const int k = tid >> 3, j4 = (tid & 7) * 4;
            __half2 h0 = __floats2half2_rn(t[j4 + 0][k], t[j4 + 1][k]);
            __half2 h1 = __floats2half2_rn(t[j4 + 2][k], t[j4 + 3][k]);
            __half* dst = g_Bh + ((size_t)(e * 32 + k)) * KR + n0 + j4;
            *(__half2*)(dst + 0) = h0;
            *(__half2*)(dst + 2) = h1;
        }
    }
}

// ---------------- main GEMM ----------------
__global__ __launch_bounds__(128, 2)
void gemm_fp16_mma(float* __restrict__ out) {
    extern __shared__ char smem[];
    const uint32_t sb = smem_u32(smem);
    const int tid  = threadIdx.x;
    const int lane = tid & 31;
    const int wid  = tid >> 5;
    const int warp_m = wid & 1;     // 2 warps over M  -> 64 rows each
    const int warp_n = wid >> 1;    // 2 warps over N  -> 64 cols each
    const int rowBase = blockIdx.y * BM;
    const int colBase = blockIdx.x * BN;

    // ---- loop-invariant cp.async addressing ----
    const int ldr = tid >> 3;                 // 0..15
    const int ldc = tid & 7;                  // 16B chunk (8 fp16)
    const __half* aSrc = g_Ah + ((size_t)rowBase + ldr) * KR + ldc * 8;
    const __half* bSrc = g_Bh + ((size_t)colBase + ldr) * KR + ldc * 8;
    const uint32_t aDst0 = sb + swoff(ldr, ldc);            // +2048*i for row+16i
    const uint32_t bDst0 = sb + A_STAGE + swoff(ldr, ldc);

    // ---- loop-invariant ldsm addressing (fp16 m16n8k16 canonical) ----
    const int lrow  = lane & 15;              // row within 16-row frag
    const int lxor  = lane & 7;               // swizzle xor
    const int lhalf = lane >> 4;              // chunk +0 / +1
    const uint32_t aBase = sb + (uint32_t)((warp_m * 64 + lrow) * 128);
    const uint32_t bBase = sb + A_STAGE + (uint32_t)((warp_n * 64 + lrow) * 128);
    uint32_t coff[4];
    #pragma unroll
    for (int ks = 0; ks < 4; ks++)
        coff[ks] = (uint32_t)(((ks * 2 + lhalf) ^ lxor) << 4);

    float acc[4][8][4];
    #pragma unroll
    for (int mi = 0; mi < 4; mi++)
        #pragma unroll
        for (int ni = 0; ni < 8; ni++)
            #pragma unroll
            for (int q = 0; q < 4; q++) acc[mi][ni][q] = 0.0f;

    // ---- fragment buffers (parity double-buffered, static indices) ----
    uint32_t a0[4][4], a1[4][4], b0[4][4], b1[4][4];

#define LDFRAG0(soff, ks) do { \
    _Pragma("unroll") for (int mi = 0; mi < 4; mi++) \
        ldsm4(a0[mi], aBase + (soff) + mi * 2048u + coff[ks]); \
    _Pragma("unroll") for (int nb = 0; nb < 4; nb++) \
        ldsm4(b0[nb], bBase + (soff) + nb * 2048u + coff[ks]); \
} while (0)
#define LDFRAG1(soff, ks) do { \
    _Pragma("unroll") for (int mi = 0; mi < 4; mi++) \
        ldsm4(a1[mi], aBase + (soff) + mi * 2048u + coff[ks]); \
    _Pragma("unroll") for (int nb = 0; nb < 4; nb++) \
        ldsm4(b1[nb], bBase + (soff) + nb * 2048u + coff[ks]); \
} while (0)
#define MMA_BURST(ab, bb) do { \
    _Pragma("unroll") for (int mi = 0; mi < 4; mi++) \
        _Pragma("unroll") for (int nb = 0; nb < 4; nb++) { \
            mma16(acc[mi][nb * 2 + 0], ab[mi], bb[nb][0], bb[nb][2]); \
            mma16(acc[mi][nb * 2 + 1], ab[mi], bb[nb][1], bb[nb][3]); \
        } \
} while (0)

    // ---- producer: issue one stage's cp.asyncs ----
#define ISSUE_STAGE(soff, aP, bP) do { \
    _Pragma("unroll") for (int i = 0; i < 8; i++) \
        cp16(aDst0 + (soff) + i * 2048u, (aP) + (size_t)i * 16 * KR); \
    _Pragma("unroll") for (int i = 0; i < 8; i++) \
        cp16(bDst0 + (soff) + i * 2048u, (bP) + (size_t)i * 16 * KR); \
} while (0)

    // ---- prologue: stages 0,1 in flight; wait s0; preload ks0 frags ----
    ISSUE_STAGE(0, aSrc, bSrc); CP_COMMIT();
    ISSUE_STAGE(STAGE_BYTES, aSrc + BK, bSrc + BK); CP_COMMIT();
    CP_WAIT1();
    __syncthreads();
    LDFRAG0(0, 0);

    uint32_t cons_off = 0;
    uint32_t prod_off = 2 * STAGE_BYTES;
    const __half* aP = aSrc + 2 * BK;
    const __half* bP = bSrc + 2 * BK;

    for (int kt = 0; kt < KTILES; kt++) {
        const uint32_t cur = cons_off;
        const uint32_t nxt = (cur + STAGE_BYTES == STAGES * STAGE_BYTES) ? 0u : cur + STAGE_BYTES;

        // top: issue stage kt+2 NOW (slot holds kt-1, fully read before last sync).
        // Unconditional commit keeps group numbering uniform for CP_WAIT1.
        if (kt + 2 < KTILES) {
            ISSUE_STAGE(prod_off, aP, bP);
            aP += BK; bP += BK;
        }
        CP_COMMIT();

        // ks0: frags in buf0; preload ks1 -> buf1
        LDFRAG1(cur, 1);
        MMA_BURST(a0, b0);
        // ks1: preload ks2 -> buf0
        LDFRAG0(cur, 2);
        MMA_BURST(a1, b1);
        // ks2: drain group kt+1 (leave kt+2 flying), preload ks3 -> buf1
        CP_WAIT1();
        LDFRAG1(cur, 3);
        MMA_BURST(a0, b0);
        // barrier: (a) all warps see stage kt+1, (b) safe to overwrite stage kt-1
        __syncthreads();
        // ks3: preload next kt's ks0 -> buf0 (branchless: last-iter read is
        // stale-but-unused data from a resident stage); mma burst
        LDFRAG0(nxt, 0);
        MMA_BURST(a1, b1);

        cons_off = nxt;
        prod_off = (prod_off + STAGE_BYTES == STAGES * STAGE_BYTES) ? 0u : prod_off + STAGE_BYTES;
    }

    // ---- epilogue: streaming stores (out is never re-read) ----
    const int g = lane >> 2, t = lane & 3;
    #pragma unroll
    for (int mi = 0; mi < 4; mi++) {
        const int r0 = rowBase + warp_m * 64 + mi * 16 + g;
        #pragma unroll
        for (int ni = 0; ni < 8; ni++) {
            const int col = colBase + warp_n * 64 + ni * 8 + t * 2;
            st_cs_f2(out + (size_t)r0 * NOUT + col, acc[mi][ni][0], acc[mi][ni][1]);
            st_cs_f2(out + (size_t)(r0 + 8) * NOUT + col, acc[mi][ni][2], acc[mi][ni][3]);
        }
    }
}

extern "C" void kernel_launch(void* const* d_in, const int* in_sizes, int n_in,
                              void* d_out, int out_size)
{
    const float* A = (const float*)d_in[0];
    const float* W = (const float*)d_in[1];
    float* out = (float*)d_out;

    cudaFuncSetAttribute(gemm_fp16_mma, cudaFuncAttributeMaxDynamicSharedMemorySize, SMEM_TOTAL);

    prep_fused<<<CONV_BLOCKS + TRANS_BLOCKS, 256>>>(A, W);
    gemm_fp16_mma<<<dim3(NOUT / BN, M_DIM / BM), 128, SMEM_TOTAL>>>(out);
}